// round 9
// baseline (speedup 1.0000x reference)
#include <cuda_runtime.h>

#define TPB 512
typedef unsigned long long u64;

// smem floats:
// srkT 12200 | sIfbn 3600 | sPart 1000 | srbk 200 | sr 100 | srn 100 |
// sbias 100 | sWro 20 | srbd 20 | srbd2f 40 | snrd2f 40 = 17420 floats = 69680 B
#define SMEM_FLOATS 17420

__device__ __forceinline__ u64 pk(float lo, float hi) {
    u64 r; asm("mov.b64 %0,{%1,%2};" : "=l"(r) : "f"(lo), "f"(hi)); return r;
}
__device__ __forceinline__ void upk(u64 v, float& lo, float& hi) {
    asm("mov.b64 {%0,%1},%2;" : "=f"(lo), "=f"(hi) : "l"(v));
}
__device__ __forceinline__ u64 fma2(u64 a, u64 b, u64 c) {
    u64 d; asm("fma.rn.f32x2 %0,%1,%2,%3;" : "=l"(d) : "l"(a), "l"(b), "l"(c)); return d;
}
__device__ __forceinline__ u64 mul2(u64 a, u64 b) {
    u64 d; asm("mul.rn.f32x2 %0,%1,%2;" : "=l"(d) : "l"(a), "l"(b)); return d;
}

__global__ void __launch_bounds__(512, 2)
rnn_kernel(const float* __restrict__ r_kc, const float* __restrict__ r_ext,
           const float* __restrict__ W0_W, const float* __restrict__ W0_w,
           const float* __restrict__ W_recur, const float* __restrict__ W_ext,
           const float* __restrict__ bias, const float* __restrict__ W_readout,
           float* __restrict__ out, int nb)
{
    const int b   = blockIdx.x;
    const int tid = threadIdx.x;
    const int wid = tid >> 5, lane = tid & 31;

    extern __shared__ float smem[];
    float* srkT   = smem;            // 12200 : rk [t*200+k], 61 steps
    float* sIfbn  = smem + 12200;    // 3600  : I_fbn [t*60+f]
    float* sPart  = smem + 15800;    // 1000  : partials, plain stride 50
    float* srbk   = smem + 16800;    // 200
    float* sr     = smem + 17000;    // 100
    float* srn    = smem + 17100;    // 100
    float* sbias  = smem + 17200;    // 100
    float* sWro   = smem + 17300;    // 20
    float* srbd   = smem + 17320;    // 20
    float* srbd2f = smem + 17340;    // 40 (u64[20])
    float* snrd2f = smem + 17380;    // 40 (u64[20])

    const float dt  = 0.5f;
    const float dtw = 0.1f;
    const u64 DT2   = pk(dt, dt);
    const u64 DTW2  = pk(dtw, dtw);
    const u64 NEG12 = pk(-1.0f, -1.0f);

    const size_t nb4000 = (size_t)nb * 4000;
    const size_t OFF_W  = (size_t)61 * nb * 100;
    const size_t OFF_WT = OFF_W + (size_t)61 * nb4000;
    const size_t OFF_RO = OFF_WT + (size_t)61 * nb4000;

    // ---- init ----
    const float* rkb = r_kc  + (size_t)b * (200 * 61);
    const float* reb = r_ext + (size_t)b * (2 * 61);
    for (int idx = tid; idx < 12200; idx += TPB) {
        int k = idx / 61, t = idx - k * 61;
        srkT[t * 200 + k] = rkb[idx];
    }
    for (int idx = tid; idx < 3600; idx += TPB) {
        int t = idx / 60, f = idx - t * 60;
        sIfbn[idx] = W_ext[2 * f] * reb[t] + W_ext[2 * f + 1] * reb[61 + t];
    }
    if (tid < 100) sbias[tid] = bias[tid];
    if (tid < 20)  { sWro[tid] = W_readout[tid]; srbd[tid] = 0.1f; }
    if (tid < 100) {
        float v = (tid < 20) ? 0.0f : 0.1f;
        sr[tid] = v;
        out[(size_t)b * 100 + tid] = v;                 // r_series[0]
    }
    if (tid == 0) out[OFF_RO + b] = 0.0f;               // readout[0]

    // ---- Wr: 4 threads per row. row s=tid>>2, quarter q=tid&3 ----
    // u64 split: base {0,13,25,38}, cnt {13,12,13,12} (float cols 0-25,26-49,50-75,76-99)
    const int s = tid >> 2, q = tid & 3;
    const int wbase = (q == 0) ? 0 : (q == 1) ? 13 : (q == 2) ? 25 : 38;
    const int wcnt  = (q & 1) ? 12 : 13;
    u64 wrr2[13];
    if (tid < 400) {
        const float2* src = (const float2*)(W_recur + s * 100) + wbase;
#pragma unroll 13
        for (int i = 0; i < 13; i++) {
            float2 v = (i < wcnt) ? src[i] : make_float2(0.f, 0.f);
            if (s < 20) {                                // MBON<-DAN zeroed
                int jcol = 2 * (wbase + i);
                if (jcol >= 80) v.x = 0.0f;
                if (jcol + 1 >= 80) v.y = 0.0f;
            }
            wrr2[i] = pk(v.x, v.y);
        }
    } else {
#pragma unroll
        for (int i = 0; i < 13; i++) wrr2[i] = 0ull;
    }

    // ---- chunk geometry: thread tid<500 owns chunks tid and tid+500 ----
    const bool dval = (tid < 500);
    const int kq = dval ? (tid % 50) : 0;
    const int m0 = dval ? (tid / 50) : 0;   // 0..9
    const int m1 = m0 + 10;                  // 10..19

    // ---- W + wt state + series[0] stores ----
    float4 rw[2];
    u64 rwt2[4];
    {
        const float4* gW0 = (const float4*)(W0_W + (size_t)b * 4000);
        const ulonglong2* gw0 = (const ulonglong2*)(W0_w + (size_t)b * 4000);
        float4* oW0  = (float4*)(out + OFF_W  + (size_t)b * 4000);
        float4* owt0 = (float4*)(out + OFF_WT + (size_t)b * 4000);
        if (dval) {
#pragma unroll
            for (int j = 0; j < 2; j++) {
                int c = tid + 500 * j;
                float4 w = gW0[c];
                ulonglong2 wt = gw0[c];
                rw[j] = w; rwt2[2 * j] = wt.x; rwt2[2 * j + 1] = wt.y;
                __stcs(oW0 + c, w);
                float a, b2, c2, d2; upk(wt.x, a, b2); upk(wt.y, c2, d2);
                __stcs(owt0 + c, make_float4(a, b2, c2, d2));
            }
        }
    }
    __syncthreads();

    // ---- rbk0 + seed sPart = W0 . rk(0) ----
    if (tid < 200) srbk[tid] = srkT[tid];
    if (dval) {
        const float4* rk4 = (const float4*)srkT;        // t = 0
        float4 x = rk4[kq];
        float4 w0 = rw[0], w1 = rw[1];
        sPart[tid]       = w0.x * x.x + w0.y * x.y + w0.z * x.z + w0.w * x.w;
        sPart[tid + 500] = w1.x * x.x + w1.y * x.y + w1.z * x.z + w1.w * x.w;
    }
    __syncthreads();

    const float* srkC = srkT;                           // rk(t) running ptr

    // ---- 60 steps, 2 barriers each ----
    for (int t = 0; t < 60; t++) {
        // ---- Phase B: 400 threads matvec (4/row), 100 threads rbk ----
        if (tid < 400) {
            const u64* rr2 = (const u64*)sr + wbase;
            u64 a0 = 0ull, a1 = 0ull;
#pragma unroll 6
            for (int i = 0; i < 12; i += 2) {
                a0 = fma2(wrr2[i],     rr2[i],     a0);
                a1 = fma2(wrr2[i + 1], rr2[i + 1], a1);
            }
            if (wcnt == 13) a0 = fma2(wrr2[12], rr2[12], a0);
            float f0, f1, f2, f3;
            upk(a0, f0, f1); upk(a1, f2, f3);
            float acc = (f0 + f1) + (f2 + f3);
            if (s < 20) {                                // I_kc partial sums
                const float* p = sPart + s * 50 + q * 12;
                int n = (q == 3) ? 14 : 12;              // q3 covers 36..49
                float b0 = 0.f, b1 = 0.f;
#pragma unroll 7
                for (int i = 0; i < 14; i += 2) {
                    if (i < n) { b0 += p[i]; b1 += p[i + 1]; }
                }
                acc += b0 + b1;
            }
            if (q == 0) {
                float I = (s >= 20 && s < 80) ? sIfbn[t * 60 + (s - 20)] : 0.0f;
                acc += sbias[s] + I;
            }
            unsigned msk = (tid < 384) ? 0xFFFFFFFFu : 0x0000FFFFu;
            acc += __shfl_xor_sync(msk, acc, 1);
            acc += __shfl_xor_sync(msk, acc, 2);
            if (q == 0) {
                float act  = fmaxf(acc, 0.0f);
                float rold = sr[s];
                float rn   = rold + (act - rold) * dt;   // TAU_R = 1
                srn[s] = rn;
                __stcs(out + ((size_t)(t + 1) * nb + b) * 100 + s, rn);
                if (s >= 80) {                           // DAN trace + packed pubs
                    int d = s - 80;
                    float nv = srbd[d] + (rn - srbd[d]) * dtw;
                    srbd[d] = nv;
                    *(u64*)(srbd2f + 2 * d) = pk(nv, nv);
                    *(u64*)(snrd2f + 2 * d) = pk(-rn, -rn);
                }
            }
        } else if (tid < 500) {
            int u = tid - 400;                           // rbk: 100 u64s, 1 each
            u64* rb2 = (u64*)srbk;
            const u64* rk2 = (const u64*)srkC;
            u64 rb = rb2[u];
            u64 d = fma2(rb, NEG12, rk2[u]);
            rb2[u] = fma2(d, DTW2, rb);
        }
        __syncthreads();

        // ---- Phase D: 2 chunks/thread, shared kq loads ----
        if (wid == 0) {                                  // readout[t+1]
            float p = (lane < 20) ? sWro[lane] * srn[lane] : 0.0f;
            p += __shfl_xor_sync(0xffffffffu, p, 16);
            p += __shfl_xor_sync(0xffffffffu, p, 8);
            p += __shfl_xor_sync(0xffffffffu, p, 4);
            p += __shfl_xor_sync(0xffffffffu, p, 2);
            p += __shfl_xor_sync(0xffffffffu, p, 1);
            if (lane == 0) out[OFF_RO + (size_t)(t + 1) * nb + b] = p;
        }
        if (dval) {
            const ulonglong2* rkv  = (const ulonglong2*)srkC;
            const ulonglong2* rnv  = (const ulonglong2*)(srkC + 200);
            const ulonglong2* rbkv = (const ulonglong2*)srbk;
            float4* oW4  = (float4*)(out + OFF_W  + ((size_t)(t + 1) * nb + b) * 4000);
            float4* owt4 = (float4*)(out + OFF_WT + ((size_t)(t + 1) * nb + b) * 4000);
            ulonglong2 rk = rkv[kq];                     // shared by both chunks
            ulonglong2 rb = rbkv[kq];
            ulonglong2 xn = rnv[kq];
#pragma unroll
            for (int j = 0; j < 2; j++) {
                int m = (j == 0) ? m0 : m1;
                int c = tid + 500 * j;
                u64 rbd2 = *(const u64*)(srbd2f + 2 * m);
                u64 nrd2 = *(const u64*)(snrd2f + 2 * m);
                u64 t0 = mul2(rbd2, rk.x);
                t0 = fma2(nrd2, rb.x, t0);
                rwt2[2 * j] = fma2(t0, DT2, rwt2[2 * j]);
                u64 t1 = mul2(rbd2, rk.y);
                t1 = fma2(nrd2, rb.y, t1);
                rwt2[2 * j + 1] = fma2(t1, DT2, rwt2[2 * j + 1]);
                float wtx, wty, wtz, wtw;
                upk(rwt2[2 * j], wtx, wty);
                upk(rwt2[2 * j + 1], wtz, wtw);
                float4 w = rw[j];
                w.x = fminf(fmaxf(fmaf(wtx - w.x, dtw, w.x), 0.0f), 0.05f);
                w.y = fminf(fmaxf(fmaf(wty - w.y, dtw, w.y), 0.0f), 0.05f);
                w.z = fminf(fmaxf(fmaf(wtz - w.z, dtw, w.z), 0.0f), 0.05f);
                w.w = fminf(fmaxf(fmaf(wtw - w.w, dtw, w.w), 0.0f), 0.05f);
                rw[j] = w;
                u64 a = mul2(pk(w.x, w.y), xn.x);
                a = fma2(pk(w.z, w.w), xn.y, a);
                float alo, ahi; upk(a, alo, ahi);
                sPart[c] = alo + ahi;                    // I_kc(t+1) partial
                __stcs(oW4 + c, w);                      // W_series[t+1]
                __stcs(owt4 + c, make_float4(wtx, wty, wtz, wtw));
            }
        }
        if (tid < 100) sr[tid] = srn[tid];               // carry r
        srkC += 200;
        __syncthreads();
    }
}

extern "C" void kernel_launch(void* const* d_in, const int* in_sizes, int n_in,
                              void* d_out, int out_size)
{
    const float* r_kc   = (const float*)d_in[0];
    const float* r_ext  = (const float*)d_in[1];
    // d_in[2] = time (dt = 0.5 exact), d_in[3] = n_batch scalar
    const float* W0_W   = (const float*)d_in[4];
    const float* W0_w   = (const float*)d_in[5];
    const float* W_rec  = (const float*)d_in[6];
    const float* W_ext  = (const float*)d_in[7];
    const float* bias   = (const float*)d_in[8];
    const float* W_ro   = (const float*)d_in[9];

    int nb = in_sizes[0] / (200 * 61);   // 256

    size_t smem = SMEM_FLOATS * sizeof(float);   // 69680 B
    cudaFuncSetAttribute(rnn_kernel, cudaFuncAttributeMaxDynamicSharedMemorySize,
                         (int)smem);

    rnn_kernel<<<nb, TPB, smem>>>(r_kc, r_ext, W0_W, W0_w, W_rec,
                                  W_ext, bias, W_ro, (float*)d_out, nb);
}

// round 10
// speedup vs baseline: 1.2141x; 1.2141x over previous
#include <cuda_runtime.h>

#define TPB 256
typedef unsigned long long u64;

// smem floats:
// srkT 12200 | sIfbn 3600 | sPart 1120 | srbk 200 | sr0 56 | sr1 56 |
// srn 100 | sbias 100 | sWro 20 | srbd 20 | srbd2f 40 | snrd2f 40 = 17552
#define SMEM_FLOATS 17552

__device__ __forceinline__ u64 pk(float lo, float hi) {
    u64 r; asm("mov.b64 %0,{%1,%2};" : "=l"(r) : "f"(lo), "f"(hi)); return r;
}
__device__ __forceinline__ void upk(u64 v, float& lo, float& hi) {
    asm("mov.b64 {%0,%1},%2;" : "=f"(lo), "=f"(hi) : "l"(v));
}
__device__ __forceinline__ u64 fma2(u64 a, u64 b, u64 c) {
    u64 d; asm("fma.rn.f32x2 %0,%1,%2,%3;" : "=l"(d) : "l"(a), "l"(b), "l"(c)); return d;
}
__device__ __forceinline__ u64 mul2(u64 a, u64 b) {
    u64 d; asm("mul.rn.f32x2 %0,%1,%2;" : "=l"(d) : "l"(a), "l"(b)); return d;
}
__device__ __forceinline__ u64 add2(u64 a, u64 b) {
    u64 d; asm("add.rn.f32x2 %0,%1,%2;" : "=l"(d) : "l"(a), "l"(b)); return d;
}

__global__ void __launch_bounds__(256, 2)
rnn_kernel(const float* __restrict__ r_kc, const float* __restrict__ r_ext,
           const float* __restrict__ W0_W, const float* __restrict__ W0_w,
           const float* __restrict__ W_recur, const float* __restrict__ W_ext,
           const float* __restrict__ bias, const float* __restrict__ W_readout,
           float* __restrict__ out, int nb)
{
    const int b   = blockIdx.x;
    const int tid = threadIdx.x;
    const int wid = tid >> 5, lane = tid & 31;

    extern __shared__ float smem[];
    float* srkT   = smem;            // 12200 : rk [t*200+k], 61 steps
    float* sIfbn  = smem + 12200;    // 3600  : I_fbn [t*60+f]
    float* sPart  = smem + 15800;    // 1120  : partials, row stride 56, gap 25..27
    float* srbk   = smem + 16920;    // 200
    float* sr0    = smem + 17120;    // 56 (floats 0..49 of r, 16B-aligned)
    float* sr1    = smem + 17176;    // 56 (floats 50..99 of r, 16B-aligned)
    float* srn    = smem + 17232;    // 100
    float* sbias  = smem + 17332;    // 100
    float* sWro   = smem + 17432;    // 20
    float* srbd   = smem + 17452;    // 20
    float* srbd2f = smem + 17472;    // 40 (u64[20])
    float* snrd2f = smem + 17512;    // 40 (u64[20])

    const float dt  = 0.5f;
    const float dtw = 0.1f;
    const u64 DT2   = pk(dt, dt);
    const u64 DTW2  = pk(dtw, dtw);
    const u64 NEG12 = pk(-1.0f, -1.0f);

    const size_t nb4000 = (size_t)nb * 4000;
    const size_t OFF_W  = (size_t)61 * nb * 100;
    const size_t OFF_WT = OFF_W + (size_t)61 * nb4000;
    const size_t OFF_RO = OFF_WT + (size_t)61 * nb4000;

    // ---- init: bulk-load rk (transposed), precompute I_fbn ----
    const float* rkb = r_kc  + (size_t)b * (200 * 61);
    const float* reb = r_ext + (size_t)b * (2 * 61);
    for (int idx = tid; idx < 12200; idx += TPB) {
        int k = idx / 61, t = idx - k * 61;
        srkT[t * 200 + k] = rkb[idx];
    }
    for (int idx = tid; idx < 3600; idx += TPB) {
        int t = idx / 60, f = idx - t * 60;
        sIfbn[idx] = W_ext[2 * f] * reb[t] + W_ext[2 * f + 1] * reb[61 + t];
    }
    if (tid < 100) sbias[tid] = bias[tid];
    if (tid < 20)  { sWro[tid] = W_readout[tid]; srbd[tid] = 0.1f; }
    if (tid < 100) {
        float v = (tid < 20) ? 0.0f : 0.1f;
        if (tid < 50) sr0[tid] = v; else sr1[tid - 50] = v;
        out[(size_t)b * 100 + tid] = v;                 // r_series[0]
    }
    if (tid == 0) out[OFF_RO + b] = 0.0f;               // readout[0]

    // ---- Wr in packed registers: thread t<200 -> row s=t>>1, half h=t&1 ----
    const int s = tid >> 1, h = tid & 1;
    u64 wrr2[25];
    if (tid < 200) {
        const float2* src = (const float2*)(W_recur + s * 100 + h * 50);
#pragma unroll
        for (int i = 0; i < 25; i++) {
            float2 v = src[i];
            if (s < 20) {                                // MBON<-DAN zeroed
                int jcol = h * 50 + 2 * i;
                if (jcol >= 80) v.x = 0.0f;
                if (jcol + 1 >= 80) v.y = 0.0f;
            }
            wrr2[i] = pk(v.x, v.y);
        }
    } else {
#pragma unroll
        for (int i = 0; i < 25; i++) wrr2[i] = 0ull;
    }

    // ---- kq-aligned chunk geometry: tid<250 owns chunks tid+250j (j=0..3),
    //      all sharing kq = tid % 50; m_j = tid/50 + 5j ----
    const bool dval = (tid < 250);
    const int kq  = dval ? (tid % 50) : 0;
    const int m0  = dval ? (tid / 50) : 0;               // 0..4
    const int kqg = kq + ((kq >= 25) ? 3 : 0);           // gap-layout column
    const int spb = m0 * 56 + kqg;                       // sPart base (j: +280)

    // ---- W (float4) + wt (packed u64) state + series[0] stores ----
    float4 rw[4];
    u64 rwt2[8];
    if (dval) {
        const float4* gW0 = (const float4*)(W0_W + (size_t)b * 4000);
        const ulonglong2* gw0 = (const ulonglong2*)(W0_w + (size_t)b * 4000);
        float4* oW0  = (float4*)(out + OFF_W  + (size_t)b * 4000);
        float4* owt0 = (float4*)(out + OFF_WT + (size_t)b * 4000);
#pragma unroll
        for (int j = 0; j < 4; j++) {
            int c = tid + 250 * j;
            float4 w = gW0[c];
            ulonglong2 wt = gw0[c];
            rw[j] = w; rwt2[2 * j] = wt.x; rwt2[2 * j + 1] = wt.y;
            __stcs(oW0 + c, w);
            float a, b2, c2, d2; upk(wt.x, a, b2); upk(wt.y, c2, d2);
            __stcs(owt0 + c, make_float4(a, b2, c2, d2));
        }
    }
    __syncthreads();

    // ---- rbk0 + seed sPart = W0 . rk(0) ----
    if (tid < 200) srbk[tid] = srkT[tid];
    if (dval) {
        const float4* rk4 = (const float4*)srkT;        // t = 0
        float4 x = rk4[kq];
#pragma unroll
        for (int j = 0; j < 4; j++) {
            float4 w = rw[j];
            sPart[spb + 280 * j] = w.x * x.x + w.y * x.y + w.z * x.z + w.w * x.w;
        }
    }
    __syncthreads();

    const float* srkC = srkT;                           // rk(t) running ptr

    // ---- 60 steps, 2 barriers each ----
    for (int t = 0; t < 60; t++) {
        // ---- Phase B: r dynamics (register matvec, LDS.128 reads) ----
        if (tid < 200) {
            const ulonglong2* rrp = (const ulonglong2*)(h ? sr1 : sr0);
            u64 a0 = 0ull, a1 = 0ull;
#pragma unroll
            for (int i = 0; i < 12; i++) {
                ulonglong2 rr = rrp[i];
                a0 = fma2(wrr2[2 * i],     rr.x, a0);
                a1 = fma2(wrr2[2 * i + 1], rr.y, a1);
            }
            a0 = fma2(wrr2[24], ((const u64*)rrp)[24], a0);
            float tail = 0.0f;
            if (s < 20) {                                // I_kc partial sums
                const u64* p2 = (const u64*)(sPart + s * 56 + h * 28);
#pragma unroll
                for (int i = 0; i < 12; i += 2) {
                    a0 = add2(a0, p2[i]);
                    a1 = add2(a1, p2[i + 1]);
                }
                tail = (sPart + s * 56 + h * 28)[24];
            }
            float f0, f1, f2, f3;
            upk(a0, f0, f1); upk(a1, f2, f3);
            float acc = (f0 + f1) + (f2 + f3) + tail;
            if (h == 0) {
                float I = (s >= 20 && s < 80) ? sIfbn[t * 60 + (s - 20)] : 0.0f;
                acc += sbias[s] + I;
            }
            unsigned msk = (tid < 192) ? 0xFFFFFFFFu : 0x000000FFu;
            acc += __shfl_xor_sync(msk, acc, 1);
            if (h == 0) {
                float act  = fmaxf(acc, 0.0f);
                float rold = (s < 50) ? sr0[s] : sr1[s - 50];
                float rn   = rold + (act - rold) * dt;   // TAU_R = 1
                srn[s] = rn;
                __stcs(out + ((size_t)(t + 1) * nb + b) * 100 + s, rn);
                if (s >= 80) {                           // DAN trace + packed pubs
                    int d = s - 80;
                    float nv = srbd[d] + (rn - srbd[d]) * dtw;
                    srbd[d] = nv;
                    *(u64*)(srbd2f + 2 * d) = pk(nv, nv);
                    *(u64*)(snrd2f + 2 * d) = pk(-rn, -rn);
                }
            }
        } else {
            int u = tid - 200;                           // rbk: 100 u64s, packed
            u64* rb2 = (u64*)srbk;
            const u64* rk2 = (const u64*)srkC;
            {
                u64 rb = rb2[u];
                u64 d = fma2(rb, NEG12, rk2[u]);
                rb2[u] = fma2(d, DTW2, rb);
            }
            if (u < 44) {
                int k = u + 56;
                u64 rb = rb2[k];
                u64 d = fma2(rb, NEG12, rk2[k]);
                rb2[k] = fma2(d, DTW2, rb);
            }
        }
        __syncthreads();

        // ---- Phase D: 4 chunks/thread, ONE shared kq load set ----
        if (wid == 0) {                                  // readout[t+1]
            float p = (lane < 20) ? sWro[lane] * srn[lane] : 0.0f;
            p += __shfl_xor_sync(0xffffffffu, p, 16);
            p += __shfl_xor_sync(0xffffffffu, p, 8);
            p += __shfl_xor_sync(0xffffffffu, p, 4);
            p += __shfl_xor_sync(0xffffffffu, p, 2);
            p += __shfl_xor_sync(0xffffffffu, p, 1);
            if (lane == 0) out[OFF_RO + (size_t)(t + 1) * nb + b] = p;
        }
        if (dval) {
            const ulonglong2* rkv  = (const ulonglong2*)srkC;
            const ulonglong2* rnv  = (const ulonglong2*)(srkC + 200);
            const ulonglong2* rbkv = (const ulonglong2*)srbk;
            float4* oW4  = (float4*)(out + OFF_W  + ((size_t)(t + 1) * nb + b) * 4000);
            float4* owt4 = (float4*)(out + OFF_WT + ((size_t)(t + 1) * nb + b) * 4000);
            ulonglong2 rk = rkv[kq];                     // shared by all 4 chunks
            ulonglong2 rb = rbkv[kq];
            ulonglong2 xn = rnv[kq];
#pragma unroll
            for (int j = 0; j < 4; j++) {
                int m = m0 + 5 * j;
                int c = tid + 250 * j;
                u64 rbd2 = *(const u64*)(srbd2f + 2 * m);
                u64 nrd2 = *(const u64*)(snrd2f + 2 * m);
                u64 t0 = mul2(rbd2, rk.x);
                t0 = fma2(nrd2, rb.x, t0);
                rwt2[2 * j] = fma2(t0, DT2, rwt2[2 * j]);
                u64 t1 = mul2(rbd2, rk.y);
                t1 = fma2(nrd2, rb.y, t1);
                rwt2[2 * j + 1] = fma2(t1, DT2, rwt2[2 * j + 1]);
                float wtx, wty, wtz, wtw;
                upk(rwt2[2 * j], wtx, wty);
                upk(rwt2[2 * j + 1], wtz, wtw);
                float4 w = rw[j];
                w.x = fminf(fmaxf(fmaf(wtx - w.x, dtw, w.x), 0.0f), 0.05f);
                w.y = fminf(fmaxf(fmaf(wty - w.y, dtw, w.y), 0.0f), 0.05f);
                w.z = fminf(fmaxf(fmaf(wtz - w.z, dtw, w.z), 0.0f), 0.05f);
                w.w = fminf(fmaxf(fmaf(wtw - w.w, dtw, w.w), 0.0f), 0.05f);
                rw[j] = w;
                u64 a = mul2(pk(w.x, w.y), xn.x);
                a = fma2(pk(w.z, w.w), xn.y, a);
                float alo, ahi; upk(a, alo, ahi);
                sPart[spb + 280 * j] = alo + ahi;        // I_kc(t+1) partial
                __stcs(oW4 + c, w);                      // W_series[t+1]
                __stcs(owt4 + c, make_float4(wtx, wty, wtz, wtw));
            }
        }
        if (tid < 100) {                                 // carry r (split layout)
            float v = srn[tid];
            if (tid < 50) sr0[tid] = v; else sr1[tid - 50] = v;
        }
        srkC += 200;
        __syncthreads();
    }
}

extern "C" void kernel_launch(void* const* d_in, const int* in_sizes, int n_in,
                              void* d_out, int out_size)
{
    const float* r_kc   = (const float*)d_in[0];
    const float* r_ext  = (const float*)d_in[1];
    // d_in[2] = time (dt = 0.5 exact), d_in[3] = n_batch scalar
    const float* W0_W   = (const float*)d_in[4];
    const float* W0_w   = (const float*)d_in[5];
    const float* W_rec  = (const float*)d_in[6];
    const float* W_ext  = (const float*)d_in[7];
    const float* bias   = (const float*)d_in[8];
    const float* W_ro   = (const float*)d_in[9];

    int nb = in_sizes[0] / (200 * 61);   // 256

    size_t smem = SMEM_FLOATS * sizeof(float);   // 70208 B
    cudaFuncSetAttribute(rnn_kernel, cudaFuncAttributeMaxDynamicSharedMemorySize,
                         (int)smem);

    rnn_kernel<<<nb, TPB, smem>>>(r_kc, r_ext, W0_W, W0_w, W_rec,
                                  W_ext, bias, W_ro, (float*)d_out, nb);
}